// round 8
// baseline (speedup 1.0000x reference)
#include <cuda_runtime.h>
#include <cuda_bf16.h>
#include <math.h>

// Problem constants
#define BB 8
#define NN 512
#define CC 37
#define CF 36        // foreground classes
#define DD 2048
#define SCORE_THR 0.1f
#define NMS_THR 0.4f

// Output layout (float32, reference return order, flattened+concatenated):
//   cls_dets  [B, CF, N, 5]  : 737280 floats, offset 0
//   kept_feats[B, N, D]      : 8388608 floats, offset 737280
//   keep      [B, CF, N]     : 147456 floats (0/1), offset 9125888
#define OUT_DETS_OFF   0
#define OUT_FEATS_OFF  737280
#define OUT_KEEP_OFF   9125888

#define FULLMASK 0xFFFFFFFFu
#define NW 8                  // max u64 words for 512 ranks

// Per-roi any-class-kept flag, duplicated per feats segment so each consumer
// warp has a private slot it reads and re-zeroes (sole reader). .bss-zeroed at
// load; re-zeroed by the consumer every call -> deterministic across replays.
__device__ int g_anykeep[2 * BB * NN];

// float -> order-preserving unsigned (finite floats)
__device__ __forceinline__ unsigned f2ord(float f) {
    unsigned u = __float_as_uint(f);
    return (u & 0x80000000u) ? ~u : (u | 0x80000000u);
}

// ---------------------------------------------------------------------------
// Kernel 1: fused decode + NMS. One block = one (b, fg-class), 512 threads.
// Invalid threads (~93%) write zeros and exit. Valid threads build an IoU
// adjacency bitmask in parallel; rank 0 does the greedy scan as bit-ops.
// Only 2 barriers after the early exit.
// ---------------------------------------------------------------------------
__global__ __launch_bounds__(512) void nms_fused_kernel(
    const float* __restrict__ rois,
    const float* __restrict__ bbox_pred,
    const float* __restrict__ scores,
    const float* __restrict__ im_info,
    float* __restrict__ out)
{
    __shared__ unsigned long long keys[NN];      // compacted valid keys
    __shared__ float4 sbox[NN];                  // sorted boxes (x1,y1,x2,y2)
    __shared__ float  sar[NN];                   // sorted areas
    __shared__ unsigned long long adj[NN][NW];   // adj[r][w]: j>r with IoU>thr
    __shared__ unsigned long long keepmask[NW];
    __shared__ int cnt;

    int tid = threadIdx.x;
    int bc  = blockIdx.x;          // b*CF + c
    int c   = bc % CF;             // fg class -> real class c+1
    int b   = bc / CF;

    if (tid == 0) cnt = 0;
    __syncthreads();

    float s = __ldg(&scores[(b * NN + tid) * CC + (c + 1)]);
    bool valid = s > SCORE_THR;

    // key: score desc, tie -> lower original index first (stable argsort)
    unsigned long long mycomp = 0ull;
    if (valid) {
        mycomp = ((unsigned long long)f2ord(s) << 32) | (unsigned)(NN - 1 - tid);
        int pos = atomicAdd(&cnt, 1);
        keys[pos] = mycomp;
    }
    __syncthreads();
    int vc = cnt;

    size_t det_base = (size_t)OUT_DETS_OFF + ((size_t)bc * NN + tid) * 5;

    if (!valid) {
        out[det_base + 0] = 0.0f;
        out[det_base + 1] = 0.0f;
        out[det_base + 2] = 0.0f;
        out[det_base + 3] = 0.0f;
        out[det_base + 4] = 0.0f;
        out[(size_t)OUT_KEEP_OFF + (size_t)bc * NN + tid] = 0.0f;
        return;
    }

    // rank by counting (stable), decode box, store at sorted position
    int rank = 0;
    for (int j = 0; j < vc; j++) rank += (keys[j] > mycomp);

    const float* rr = rois + (b * NN + tid) * 5;
    float rx1 = __ldg(rr + 1), ry1 = __ldg(rr + 2);
    float rx2 = __ldg(rr + 3), ry2 = __ldg(rr + 4);
    float w  = rx2 - rx1;
    float h  = ry2 - ry1;
    float cx = rx1 + 0.5f * w;
    float cy = ry1 + 0.5f * h;

    const float* dp = bbox_pred + ((b * NN + tid) * CC + (c + 1)) * 4;
    float d0 = __ldg(dp + 0) * 0.1f;
    float d1 = __ldg(dp + 1) * 0.1f;
    float d2 = __ldg(dp + 2) * 0.2f;
    float d3 = __ldg(dp + 3) * 0.2f;

    float px = d0 * w + cx;
    float py = d1 * h + cy;
    float pw = expf(d2) * w;
    float ph = expf(d3) * h;

    float xmax = __ldg(&im_info[b * 3 + 1]) - 1.0f;
    float ymax = __ldg(&im_info[b * 3 + 0]) - 1.0f;
    float mx1 = fminf(fmaxf(px - 0.5f * pw, 0.0f), xmax);
    float my1 = fminf(fmaxf(py - 0.5f * ph, 0.0f), ymax);
    float mx2 = fminf(fmaxf(px + 0.5f * pw, 0.0f), xmax);
    float my2 = fminf(fmaxf(py + 0.5f * ph, 0.0f), ymax);
    float marea = (mx2 - mx1) * (my2 - my1);

    sbox[rank] = make_float4(mx1, my1, mx2, my2);
    sar[rank]  = marea;
    __syncthreads();   // valid threads only

    // parallel adjacency: bits for ranks j > rank with IoU > thr
    int W = (vc + 63) >> 6;
    {
        unsigned long long a[NW];
        #pragma unroll
        for (int ww = 0; ww < NW; ww++) a[ww] = 0ull;
        for (int j = rank + 1; j < vc; j++) {
            float4 bj = sbox[j];
            float lx = fmaxf(mx1, bj.x);
            float ly = fmaxf(my1, bj.y);
            float rx = fminf(mx2, bj.z);
            float ry = fminf(my2, bj.w);
            float iw = fmaxf(rx - lx, 0.0f);
            float ih = fmaxf(ry - ly, 0.0f);
            float inter = iw * ih;
            float iou = inter / (marea + sar[j] - inter + 1e-9f);
            if (iou > NMS_THR) a[j >> 6] |= (1ull << (j & 63));
        }
        for (int ww = 0; ww < W; ww++) adj[rank][ww] = a[ww];
    }
    __syncthreads();

    // rank 0: serial greedy scan over bitmasks (expected W==1, vc ~ 35)
    if (rank == 0) {
        unsigned long long supp[NW], km[NW];
        #pragma unroll
        for (int ww = 0; ww < NW; ww++) { supp[ww] = 0ull; km[ww] = 0ull; }
        for (int i = 0; i < vc; i++) {
            if (!((supp[i >> 6] >> (i & 63)) & 1ull)) {
                km[i >> 6] |= (1ull << (i & 63));
                for (int ww = 0; ww < W; ww++) supp[ww] |= adj[i][ww];
            }
        }
        for (int ww = 0; ww < W; ww++) keepmask[ww] = km[ww];
    }
    __syncthreads();

    bool k = (keepmask[rank >> 6] >> (rank & 63)) & 1ull;
    if (k) {
        out[det_base + 0] = mx1;
        out[det_base + 1] = my1;
        out[det_base + 2] = mx2;
        out[det_base + 3] = my2;
        out[det_base + 4] = s;
        atomicOr(&g_anykeep[b * NN + tid], 1);
        atomicOr(&g_anykeep[BB * NN + b * NN + tid], 1);
    } else {
        out[det_base + 0] = 0.0f;
        out[det_base + 1] = 0.0f;
        out[det_base + 2] = 0.0f;
        out[det_base + 3] = 0.0f;
        out[det_base + 4] = 0.0f;
    }
    out[(size_t)OUT_KEEP_OFF + (size_t)bc * NN + tid] = k ? 1.0f : 0.0f;
}

// ---------------------------------------------------------------------------
// Kernel 2: masked feature copy. One warp per HALF row (8 float4/lane),
// 8192 warps total -> 1024 blocks. Each warp's lane 0 is the sole reader and
// clearer of its private flag copy; no barriers anywhere.
// ---------------------------------------------------------------------------
__global__ __launch_bounds__(256) void feats_kernel(
    const float4* __restrict__ feats,
    float* __restrict__ out)
{
    int wid  = blockIdx.x * 8 + (threadIdx.x >> 5);  // 0..8191
    int row  = wid >> 1;                             // b*NN + n, 0..4095
    int seg  = wid & 1;                              // half-row segment
    int lane = threadIdx.x & 31;

    int any = 0;
    if (lane == 0) {
        int* slot = &g_anykeep[seg * (BB * NN) + row];
        any = *slot;
        if (any) *slot = 0;   // restore zero-invariant for next call
    }
    any = __shfl_sync(FULLMASK, any, 0);

    const float4* src = feats + (size_t)row * (DD / 4) + seg * (DD / 8);
    float4* dst = (float4*)(out + OUT_FEATS_OFF) + (size_t)row * (DD / 4) + seg * (DD / 8);

    if (any) {
        #pragma unroll
        for (int i = 0; i < DD / 8 / 32; i++)      // 8 float4 per lane
            dst[lane + 32 * i] = __ldg(&src[lane + 32 * i]);
    } else {
        float4 z = make_float4(0.f, 0.f, 0.f, 0.f);
        #pragma unroll
        for (int i = 0; i < DD / 8 / 32; i++)
            dst[lane + 32 * i] = z;
    }
}

extern "C" void kernel_launch(void* const* d_in, const int* in_sizes, int n_in,
                              void* d_out, int out_size) {
    const float* rois      = (const float*)d_in[0];
    const float* bbox_pred = (const float*)d_in[1];
    const float* scores    = (const float*)d_in[2];
    const float* im_info   = (const float*)d_in[3];
    const float* feats     = (const float*)d_in[4];
    float* out = (float*)d_out;

    nms_fused_kernel<<<BB * CF, 512>>>(rois, bbox_pred, scores, im_info, out);
    feats_kernel<<<2 * BB * NN / 8, 256>>>((const float4*)feats, out);
}

// round 9
// speedup vs baseline: 1.0561x; 1.0561x over previous
#include <cuda_runtime.h>
#include <cuda_bf16.h>
#include <math.h>

// Problem constants
#define BB 8
#define NN 512
#define CC 37
#define CF 36        // foreground classes
#define DD 2048
#define SCORE_THR 0.1f
#define NMS_THR 0.4f

// Output layout (float32, reference return order, flattened+concatenated):
//   cls_dets  [B, CF, N, 5]  : 737280 floats, offset 0
//   kept_feats[B, N, D]      : 8388608 floats, offset 737280
//   keep      [B, CF, N]     : 147456 floats (0/1), offset 9125888
#define OUT_DETS_OFF   0
#define OUT_FEATS_OFF  737280
#define OUT_KEEP_OFF   9125888

#define DETS_F4   184320     // 737280/4
#define KEEP_F4   36864      // 147456/4
#define ZERO_F4   (DETS_F4 + KEEP_F4)   // 221184 = 432*512

#define FULLMASK 0xFFFFFFFFu

// Scratch. g_cnt/g_keys are fully (over)written by K1 every call before K2
// reads them. g_anykeep is .bss-zeroed at load and re-zeroed by its sole
// reader (feats lane 0) every call -> deterministic across graph replays.
__device__ unsigned long long g_keys[BB * CF * NN];
__device__ int g_cnt[BB * CF];
__device__ int g_anykeep[BB * NN];

// float -> order-preserving unsigned (positive finite floats)
__device__ __forceinline__ unsigned f2ord(float f) {
    return __float_as_uint(f) | 0x80000000u;
}
__device__ __forceinline__ float ord2f(unsigned o) {
    return __uint_as_float(o & 0x7FFFFFFFu);
}

// ---------------------------------------------------------------------------
// K1 prep: blocks 0..7 compact valid (score>thr) boxes per batch with
// coalesced score reads; blocks 8..439 zero the dets+keep output regions.
// ---------------------------------------------------------------------------
__global__ __launch_bounds__(512) void prep_kernel(
    const float* __restrict__ scores,
    float* __restrict__ out)
{
    int tid = threadIdx.x;
    int bid = blockIdx.x;

    if (bid >= BB) {
        // zero-fill dets + keep regions (float4 streams)
        int zidx = (bid - BB) * 512 + tid;
        float4 z = make_float4(0.f, 0.f, 0.f, 0.f);
        if (zidx < DETS_F4)
            ((float4*)out)[zidx] = z;
        else
            ((float4*)(out + OUT_KEEP_OFF))[zidx - DETS_F4] = z;
        return;
    }

    // compaction for batch b = bid; thread owns roi n = tid
    __shared__ int scnt[CF];
    if (tid < CF) scnt[tid] = 0;
    __syncthreads();

    int b = bid;
    const float* srow = scores + (size_t)(b * NN + tid) * CC;
    #pragma unroll 4
    for (int c = 1; c < CC; c++) {
        float s = __ldg(srow + c);
        if (s > SCORE_THR) {
            int fc = c - 1;
            int pos = atomicAdd(&scnt[fc], 1);
            // key: score desc, tie -> lower original index first
            g_keys[(size_t)(b * CF + fc) * NN + pos] =
                ((unsigned long long)f2ord(s) << 32) | (unsigned)(NN - 1 - tid);
        }
    }
    __syncthreads();
    if (tid < CF) g_cnt[b * CF + tid] = scnt[tid];
}

// ---------------------------------------------------------------------------
// K2 NMS-proper: one block per (b, fg-class). Only the first cnt threads stay
// alive (~40). Decode, stable rank-by-count, barrier-greedy among ~2 warps.
// Only KEPT threads write (zeros already laid down by K1).
// ---------------------------------------------------------------------------
__global__ __launch_bounds__(512) void nms_kernel(
    const float* __restrict__ rois,
    const float* __restrict__ bbox_pred,
    const float* __restrict__ im_info,
    float* __restrict__ out)
{
    __shared__ unsigned long long skeys[NN];
    __shared__ float sx1[NN], sy1[NN], sx2[NN], sy2[NN], sar[NN];
    __shared__ int   keepflag[NN];

    int tid = threadIdx.x;
    int bc  = blockIdx.x;          // b*CF + c
    int c   = bc % CF;             // fg class -> real class c+1
    int b   = bc / CF;

    int cnt = g_cnt[bc];
    if (tid >= cnt) return;       // nothing to write: zeros pre-laid by K1

    unsigned long long key = g_keys[(size_t)bc * NN + tid];
    int n = NN - 1 - (int)(key & 0xFFFFFFFFu);
    float s = ord2f((unsigned)(key >> 32));
    skeys[tid] = key;

    // issue decode loads immediately (overlap with ranking)
    const float* rr = rois + (b * NN + n) * 5;
    float rx1 = __ldg(rr + 1), ry1 = __ldg(rr + 2);
    float rx2 = __ldg(rr + 3), ry2 = __ldg(rr + 4);
    const float* dp = bbox_pred + ((b * NN + n) * CC + (c + 1)) * 4;
    float d0 = __ldg(dp + 0) * 0.1f;
    float d1 = __ldg(dp + 1) * 0.1f;
    float d2 = __ldg(dp + 2) * 0.2f;
    float d3 = __ldg(dp + 3) * 0.2f;
    float xmax = __ldg(&im_info[b * 3 + 1]) - 1.0f;
    float ymax = __ldg(&im_info[b * 3 + 0]) - 1.0f;

    float w  = rx2 - rx1;
    float h  = ry2 - ry1;
    float cx = rx1 + 0.5f * w;
    float cy = ry1 + 0.5f * h;
    float px = d0 * w + cx;
    float py = d1 * h + cy;
    float pw = expf(d2) * w;
    float ph = expf(d3) * h;
    float mx1 = fminf(fmaxf(px - 0.5f * pw, 0.0f), xmax);
    float my1 = fminf(fmaxf(py - 0.5f * ph, 0.0f), ymax);
    float mx2 = fminf(fmaxf(px + 0.5f * pw, 0.0f), xmax);
    float my2 = fminf(fmaxf(py + 0.5f * ph, 0.0f), ymax);
    float marea = (mx2 - mx1) * (my2 - my1);

    __syncthreads();   // skeys visible

    // stable rank by counting (list order from atomics is nondeterministic,
    // ranks are not)
    int rank = 0;
    for (int j = 0; j < cnt; j++) rank += (skeys[j] > key);

    sx1[rank] = mx1; sy1[rank] = my1;
    sx2[rank] = mx2; sy2[rank] = my2;
    sar[rank] = marea;
    __syncthreads();

    // barrier-greedy over sorted prefix (~cnt threads = ~2 warps)
    for (int i = 0; i < cnt; i++) {
        bool sup = false;
        if (rank < i && keepflag[rank]) {
            float lx = fmaxf(mx1, sx1[i]);
            float ly = fmaxf(my1, sy1[i]);
            float rx = fminf(mx2, sx2[i]);
            float ry = fminf(my2, sy2[i]);
            float iw = fmaxf(rx - lx, 0.0f);
            float ih = fmaxf(ry - ly, 0.0f);
            float inter = iw * ih;
            float iou = inter / (marea + sar[i] - inter + 1e-9f);
            sup = iou > NMS_THR;
        }
        int any = __syncthreads_or((int)sup);
        if (rank == i) keepflag[i] = any ? 0 : 1;
        __syncthreads();
    }

    if (keepflag[rank]) {
        size_t det_base = (size_t)OUT_DETS_OFF + ((size_t)bc * NN + n) * 5;
        out[det_base + 0] = mx1;
        out[det_base + 1] = my1;
        out[det_base + 2] = mx2;
        out[det_base + 3] = my2;
        out[det_base + 4] = s;
        out[(size_t)OUT_KEEP_OFF + (size_t)bc * NN + n] = 1.0f;
        atomicOr(&g_anykeep[b * NN + n], 1);
    }
}

// ---------------------------------------------------------------------------
// K3 feats: warp-per-row masked copy (R5 best variant). Lane 0 is the sole
// reader+clearer of its g_anykeep slot; no barriers.
// ---------------------------------------------------------------------------
__global__ __launch_bounds__(256) void feats_kernel(
    const float4* __restrict__ feats,
    float* __restrict__ out)
{
    int row  = blockIdx.x * 8 + (threadIdx.x >> 5);   // b*NN + n, 0..4095
    int lane = threadIdx.x & 31;

    int any = 0;
    if (lane == 0) {
        any = g_anykeep[row];
        if (any) g_anykeep[row] = 0;   // restore zero-invariant for next call
    }
    any = __shfl_sync(FULLMASK, any, 0);

    const float4* src = feats + (size_t)row * (DD / 4);
    float4* dst = (float4*)(out + OUT_FEATS_OFF) + (size_t)row * (DD / 4);

    if (any) {
        #pragma unroll
        for (int i = 0; i < DD / 4 / 32; i++)     // 16 float4 per lane
            dst[lane + 32 * i] = __ldg(&src[lane + 32 * i]);
    } else {
        float4 z = make_float4(0.f, 0.f, 0.f, 0.f);
        #pragma unroll
        for (int i = 0; i < DD / 4 / 32; i++)
            dst[lane + 32 * i] = z;
    }
}

// launch-slot pad so ncu's fixed capture index lands on nms_kernel
__global__ void nop_kernel() {}

extern "C" void kernel_launch(void* const* d_in, const int* in_sizes, int n_in,
                              void* d_out, int out_size) {
    const float* rois      = (const float*)d_in[0];
    const float* bbox_pred = (const float*)d_in[1];
    const float* scores    = (const float*)d_in[2];
    const float* im_info   = (const float*)d_in[3];
    const float* feats     = (const float*)d_in[4];
    float* out = (float*)d_out;

    prep_kernel<<<BB + ZERO_F4 / 512, 512>>>(scores, out);
    nms_kernel<<<BB * CF, 512>>>(rois, bbox_pred, im_info, out);
    feats_kernel<<<BB * NN / 8, 256>>>((const float4*)feats, out);
    nop_kernel<<<1, 32>>>();
}

// round 10
// speedup vs baseline: 1.1969x; 1.1333x over previous
#include <cuda_runtime.h>
#include <cuda_bf16.h>
#include <math.h>

// Problem constants
#define BB 8
#define NN 512
#define CC 37
#define CF 36        // foreground classes
#define DD 2048
#define SCORE_THR 0.1f
#define NMS_THR 0.4f

// Output layout (float32, reference return order, flattened+concatenated):
//   cls_dets  [B, CF, N, 5]  : 737280 floats, offset 0
//   kept_feats[B, N, D]      : 8388608 floats, offset 737280
//   keep      [B, CF, N]     : 147456 floats (0/1), offset 9125888
#define OUT_DETS_OFF   0
#define OUT_FEATS_OFF  737280
#define OUT_KEEP_OFF   9125888

#define GRID (BB * CF)       // 288 blocks; all co-resident (148 SMs x >=2)
#define FULLMASK 0xFFFFFFFFu

// All-zero on entry of every call:
//  - g_anykeep: .bss-zeroed at load; consumed+cleared via atomicExch each call.
//  - g_bar1/g_bar2: .bss-zeroed; last arriver at bar2 resets both each call.
__device__ int g_anykeep[BB * NN];
__device__ int g_bar1;
__device__ int g_bar2;

// float -> order-preserving unsigned (positive finite floats)
__device__ __forceinline__ unsigned f2ord(float f) {
    return __float_as_uint(f) | 0x80000000u;
}

// ---------------------------------------------------------------------------
// Single fused kernel: one block per (b, fg-class).
// Phase A: compact valid boxes, decode, stable rank.
// Phase B: greedy NMS (rank-threads, ONE barrier per iteration).
// Phase C: per-thread output writes (owner thread writes its own det slot).
// Phase D: grid-wide barrier, then warp-per-row masked feature copy.
// ---------------------------------------------------------------------------
__global__ __launch_bounds__(512, 2) void fused_kernel(
    const float*  __restrict__ rois,
    const float*  __restrict__ bbox_pred,
    const float*  __restrict__ scores,
    const float*  __restrict__ im_info,
    const float4* __restrict__ feats,
    float* __restrict__ out)
{
    __shared__ unsigned long long keys[NN];     // compacted valid keys
    __shared__ float sx1[NN], sy1[NN], sx2[NN], sy2[NN], sar[NN];
    __shared__ int   keepflag[NN];              // per sorted rank
    __shared__ int   cnt;

    int tid = threadIdx.x;
    int bc  = blockIdx.x;          // b*CF + c
    int c   = bc % CF;             // fg class -> real class c+1
    int b   = bc / CF;

    if (tid == 0) cnt = 0;
    __syncthreads();

    // ---- Phase A: validity + compaction ----
    float s = __ldg(&scores[(b * NN + tid) * CC + (c + 1)]);
    bool valid = s > SCORE_THR;

    unsigned long long mykey = 0ull;
    if (valid) {
        // score desc, tie -> lower original index first (stable argsort)
        mykey = ((unsigned long long)f2ord(s) << 32) | (unsigned)(NN - 1 - tid);
        keys[atomicAdd(&cnt, 1)] = mykey;
    }
    __syncthreads();
    int vc = cnt;

    // decode + stable rank-by-count (valid threads only)
    float mx1 = 0.f, my1 = 0.f, mx2 = 0.f, my2 = 0.f;
    int myrank = 0;
    if (valid) {
        for (int j = 0; j < vc; j++) myrank += (keys[j] > mykey);

        const float* rr = rois + (b * NN + tid) * 5;
        float rx1 = __ldg(rr + 1), ry1 = __ldg(rr + 2);
        float rx2 = __ldg(rr + 3), ry2 = __ldg(rr + 4);
        float w  = rx2 - rx1;
        float h  = ry2 - ry1;
        float cx = rx1 + 0.5f * w;
        float cy = ry1 + 0.5f * h;

        const float* dp = bbox_pred + ((b * NN + tid) * CC + (c + 1)) * 4;
        float d0 = __ldg(dp + 0) * 0.1f;
        float d1 = __ldg(dp + 1) * 0.1f;
        float d2 = __ldg(dp + 2) * 0.2f;
        float d3 = __ldg(dp + 3) * 0.2f;

        float px = d0 * w + cx;
        float py = d1 * h + cy;
        float pw = expf(d2) * w;
        float ph = expf(d3) * h;

        float xmax = __ldg(&im_info[b * 3 + 1]) - 1.0f;
        float ymax = __ldg(&im_info[b * 3 + 0]) - 1.0f;
        mx1 = fminf(fmaxf(px - 0.5f * pw, 0.0f), xmax);
        my1 = fminf(fmaxf(py - 0.5f * ph, 0.0f), ymax);
        mx2 = fminf(fmaxf(px + 0.5f * pw, 0.0f), xmax);
        my2 = fminf(fmaxf(py + 0.5f * ph, 0.0f), ymax);

        sx1[myrank] = mx1; sy1[myrank] = my1;
        sx2[myrank] = mx2; sy2[myrank] = my2;
        sar[myrank] = (mx2 - mx1) * (my2 - my1);
    }
    __syncthreads();

    // ---- Phase B: greedy NMS; thread tid handles rank tid ----
    // keepflag[tid] is only ever read by thread tid (written by itself at
    // iteration i == tid) -> ONE barrier per iteration suffices.
    float gx1 = 0.f, gy1 = 0.f, gx2 = 0.f, gy2 = 0.f, garea = 0.f;
    if (tid < vc) {
        gx1 = sx1[tid]; gy1 = sy1[tid];
        gx2 = sx2[tid]; gy2 = sy2[tid];
        garea = sar[tid];
    }
    for (int i = 0; i < vc; i++) {
        bool sup = false;
        if (tid < i && keepflag[tid]) {
            float lx = fmaxf(gx1, sx1[i]);
            float ly = fmaxf(gy1, sy1[i]);
            float rx = fminf(gx2, sx2[i]);
            float ry = fminf(gy2, sy2[i]);
            float iw = fmaxf(rx - lx, 0.0f);
            float ih = fmaxf(ry - ly, 0.0f);
            float inter = iw * ih;
            float iou = inter / (garea + sar[i] - inter + 1e-9f);
            sup = iou > NMS_THR;
        }
        int any = __syncthreads_or((int)sup);
        if (tid == i) keepflag[i] = any ? 0 : 1;
    }
    __syncthreads();   // last keepflag write visible to owner threads

    // ---- Phase C: output (thread tid owns roi n = tid of this (b,c)) ----
    bool k = valid && (keepflag[myrank] != 0);
    size_t det_base = (size_t)OUT_DETS_OFF + ((size_t)bc * NN + tid) * 5;
    if (k) {
        out[det_base + 0] = mx1;
        out[det_base + 1] = my1;
        out[det_base + 2] = mx2;
        out[det_base + 3] = my2;
        out[det_base + 4] = s;
        atomicOr(&g_anykeep[b * NN + tid], 1);
    } else {
        out[det_base + 0] = 0.0f;
        out[det_base + 1] = 0.0f;
        out[det_base + 2] = 0.0f;
        out[det_base + 3] = 0.0f;
        out[det_base + 4] = 0.0f;
    }
    out[(size_t)OUT_KEEP_OFF + (size_t)bc * NN + tid] = k ? 1.0f : 0.0f;

    // ---- Phase D: grid-wide barrier (all 288 blocks are co-resident) ----
    __threadfence();
    __syncthreads();
    if (tid == 0) {
        atomicAdd(&g_bar1, 1);
        while (atomicAdd(&g_bar1, 0) < GRID) __nanosleep(64);
    }
    __syncthreads();
    __threadfence();
    if (tid == 0) {
        int r = atomicAdd(&g_bar2, 1);
        if (r == GRID - 1) {               // last arriver: all spins exited,
            atomicExch(&g_bar1, 0);        // all bar2 increments done ->
            atomicExch(&g_bar2, 0);        // safe to reset both for next call
        }
    }

    // ---- masked feature copy: warp w handles row w ----
    int w = bc * 16 + (tid >> 5);          // 0..4607; rows 0..4095 live
    if (w < BB * NN) {
        int lane = tid & 31;
        int any = 0;
        if (lane == 0)
            any = atomicExch(&g_anykeep[w], 0);   // read+clear in one L2 op
        any = __shfl_sync(FULLMASK, any, 0);

        const float4* src = feats + (size_t)w * (DD / 4);
        float4* dst = (float4*)(out + OUT_FEATS_OFF) + (size_t)w * (DD / 4);

        if (any) {
            #pragma unroll
            for (int i = 0; i < DD / 4 / 32; i++)   // 16 float4 per lane
                dst[lane + 32 * i] = __ldg(&src[lane + 32 * i]);
        } else {
            float4 z = make_float4(0.f, 0.f, 0.f, 0.f);
            #pragma unroll
            for (int i = 0; i < DD / 4 / 32; i++)
                dst[lane + 32 * i] = z;
        }
    }
}

extern "C" void kernel_launch(void* const* d_in, const int* in_sizes, int n_in,
                              void* d_out, int out_size) {
    const float* rois      = (const float*)d_in[0];
    const float* bbox_pred = (const float*)d_in[1];
    const float* scores    = (const float*)d_in[2];
    const float* im_info   = (const float*)d_in[3];
    const float* feats     = (const float*)d_in[4];
    float* out = (float*)d_out;

    fused_kernel<<<GRID, 512>>>(rois, bbox_pred, scores, im_info,
                                (const float4*)feats, out);
}

// round 11
// speedup vs baseline: 1.2616x; 1.0541x over previous
#include <cuda_runtime.h>
#include <cuda_bf16.h>
#include <math.h>

// Problem constants
#define BB 8
#define NN 512
#define CC 37
#define CF 36        // foreground classes
#define DD 2048
#define SCORE_THR 0.1f
#define NMS_THR 0.4f

// Output layout (float32, reference return order, flattened+concatenated):
//   cls_dets  [B, CF, N, 5]  : 737280 floats, offset 0
//   kept_feats[B, N, D]      : 8388608 floats, offset 737280
//   keep      [B, CF, N]     : 147456 floats (0/1), offset 9125888
#define OUT_DETS_OFF   0
#define OUT_FEATS_OFF  737280
#define OUT_KEEP_OFF   9125888

#define GRID (BB * CF)       // 288 blocks; all co-resident (148 SMs x 2 = 296)
#define FULLMASK 0xFFFFFFFFu

// All-zero on entry of every call (graph-replay safe):
//  - g_anykeep: .bss-zeroed; consumed+cleared via atomicExch each call.
//  - g_done/g_done2: .bss-zeroed; 32nd consumer of each batch resets both.
__device__ int g_anykeep[BB * NN];
__device__ int g_done[BB];
__device__ int g_done2[BB];

// float -> order-preserving unsigned (positive finite floats)
__device__ __forceinline__ unsigned f2ord(float f) {
    return __float_as_uint(f) | 0x80000000u;
}

// OR-reduction barrier among the first `count` threads (named barrier 1).
__device__ __forceinline__ int bar1_red_or(int count, int pred) {
    int r;
    asm volatile(
        "{\n\t"
        ".reg .pred p, q;\n\t"
        "setp.ne.s32 p, %2, 0;\n\t"
        "bar.red.or.pred q, 1, %1, p;\n\t"
        "selp.b32 %0, 1, 0, q;\n\t"
        "}"
        : "=r"(r) : "r"(count), "r"(pred));
    return r;
}

// ---------------------------------------------------------------------------
// Single fused kernel: one block per (b, fg-class).
// A: compact valid boxes, decode, stable rank.
// B: greedy NMS among only ceil(vc/32) warps (named barrier 1); other warps
//    wait once at barrier 0.
// C: per-thread output writes; per-batch done counter.
// D: per-batch wait, then warp-per-row masked feature copy (blocks bc<256).
// ---------------------------------------------------------------------------
__global__ __launch_bounds__(512, 2) void fused_kernel(
    const float*  __restrict__ rois,
    const float*  __restrict__ bbox_pred,
    const float*  __restrict__ scores,
    const float*  __restrict__ im_info,
    const float4* __restrict__ feats,
    float* __restrict__ out)
{
    __shared__ unsigned long long keys[NN];     // compacted valid keys
    __shared__ float sx1[NN], sy1[NN], sx2[NN], sy2[NN], sar[NN];
    __shared__ int   keepflag[NN];              // per sorted rank
    __shared__ int   cnt;

    int tid = threadIdx.x;
    int bc  = blockIdx.x;          // b*CF + c
    int c   = bc % CF;             // fg class -> real class c+1
    int b   = bc / CF;

    if (tid == 0) cnt = 0;
    __syncthreads();

    // ---- Phase A: validity + compaction ----
    float s = __ldg(&scores[(b * NN + tid) * CC + (c + 1)]);
    bool valid = s > SCORE_THR;

    unsigned long long mykey = 0ull;
    if (valid) {
        // score desc, tie -> lower original index first (stable argsort)
        mykey = ((unsigned long long)f2ord(s) << 32) | (unsigned)(NN - 1 - tid);
        keys[atomicAdd(&cnt, 1)] = mykey;
    }
    __syncthreads();
    int vc = cnt;

    // decode + stable rank-by-count (valid threads only)
    float mx1 = 0.f, my1 = 0.f, mx2 = 0.f, my2 = 0.f;
    int myrank = 0;
    if (valid) {
        for (int j = 0; j < vc; j++) myrank += (keys[j] > mykey);

        const float* rr = rois + (b * NN + tid) * 5;
        float rx1 = __ldg(rr + 1), ry1 = __ldg(rr + 2);
        float rx2 = __ldg(rr + 3), ry2 = __ldg(rr + 4);
        float w  = rx2 - rx1;
        float h  = ry2 - ry1;
        float cx = rx1 + 0.5f * w;
        float cy = ry1 + 0.5f * h;

        const float* dp = bbox_pred + ((b * NN + tid) * CC + (c + 1)) * 4;
        float d0 = __ldg(dp + 0) * 0.1f;
        float d1 = __ldg(dp + 1) * 0.1f;
        float d2 = __ldg(dp + 2) * 0.2f;
        float d3 = __ldg(dp + 3) * 0.2f;

        float px = d0 * w + cx;
        float py = d1 * h + cy;
        float pw = expf(d2) * w;
        float ph = expf(d3) * h;

        float xmax = __ldg(&im_info[b * 3 + 1]) - 1.0f;
        float ymax = __ldg(&im_info[b * 3 + 0]) - 1.0f;
        mx1 = fminf(fmaxf(px - 0.5f * pw, 0.0f), xmax);
        my1 = fminf(fmaxf(py - 0.5f * ph, 0.0f), ymax);
        mx2 = fminf(fmaxf(px + 0.5f * pw, 0.0f), xmax);
        my2 = fminf(fmaxf(py + 0.5f * ph, 0.0f), ymax);

        sx1[myrank] = mx1; sy1[myrank] = my1;
        sx2[myrank] = mx2; sy2[myrank] = my2;
        sar[myrank] = (mx2 - mx1) * (my2 - my1);
    }
    __syncthreads();

    // ---- Phase B: greedy NMS among first P32 threads only ----
    // Thread tid handles rank tid; own kept-status lives in a register
    // (decided at iteration i == tid). Other warps skip to barrier 0.
    int P32 = ((vc + 31) >> 5) << 5;
    if (tid < P32) {
        float gx1 = 0.f, gy1 = 0.f, gx2 = 0.f, gy2 = 0.f, garea = 0.f;
        if (tid < vc) {
            gx1 = sx1[tid]; gy1 = sy1[tid];
            gx2 = sx2[tid]; gy2 = sy2[tid];
            garea = sar[tid];
        }
        bool alive = false;     // becomes valid at i == tid
        for (int i = 0; i < vc; i++) {
            bool sup = false;
            if (tid < i && alive) {
                float lx = fmaxf(gx1, sx1[i]);
                float ly = fmaxf(gy1, sy1[i]);
                float rx = fminf(gx2, sx2[i]);
                float ry = fminf(gy2, sy2[i]);
                float iw = fmaxf(rx - lx, 0.0f);
                float ih = fmaxf(ry - ly, 0.0f);
                float inter = iw * ih;
                float iou = inter / (garea + sar[i] - inter + 1e-9f);
                sup = iou > NMS_THR;
            }
            int any = bar1_red_or(P32, (int)sup);
            if (tid == i) {
                alive = !any;
                keepflag[i] = alive ? 1 : 0;
            }
        }
    }
    __syncthreads();   // releases when greedy warps arrive too

    // ---- Phase C: output (thread tid owns roi n = tid of this (b,c)) ----
    bool k = valid && (keepflag[myrank] != 0);
    size_t det_base = (size_t)OUT_DETS_OFF + ((size_t)bc * NN + tid) * 5;
    if (k) {
        out[det_base + 0] = mx1;
        out[det_base + 1] = my1;
        out[det_base + 2] = mx2;
        out[det_base + 3] = my2;
        out[det_base + 4] = s;
        atomicOr(&g_anykeep[b * NN + tid], 1);
    } else {
        out[det_base + 0] = 0.0f;
        out[det_base + 1] = 0.0f;
        out[det_base + 2] = 0.0f;
        out[det_base + 3] = 0.0f;
        out[det_base + 4] = 0.0f;
    }
    out[(size_t)OUT_KEEP_OFF + (size_t)bc * NN + tid] = k ? 1.0f : 0.0f;

    // publish this (b,c)'s completion
    __threadfence();
    __syncthreads();
    if (tid == 0) atomicAdd(&g_done[b], 1);

    // ---- Phase D: per-batch wait + masked feature copy ----
    // Blocks bc < 256 each own 16 rows: rows bc*16 .. bc*16+15, all in batch
    // fb = bc/32 (512 rows/batch = 32 blocks/batch). Blocks 256..287 exit.
    if (bc >= (BB * NN) / 16) return;
    int fb = bc >> 5;

    if (tid == 0) {
        while (atomicAdd(&g_done[fb], 0) < CF) __nanosleep(32);
        __threadfence();                       // acquire before anykeep reads
        int r = atomicAdd(&g_done2[fb], 1);
        if (r == 31) {                         // last consumer past the spin:
            atomicExch(&g_done[fb], 0);        // safe to reset both counters
            atomicExch(&g_done2[fb], 0);
        }
    }
    __syncthreads();

    int row  = bc * 16 + (tid >> 5);           // b*NN + n
    int lane = tid & 31;

    int any = 0;
    if (lane == 0)
        any = atomicExch(&g_anykeep[row], 0);  // read+clear in one L2 op
    any = __shfl_sync(FULLMASK, any, 0);

    const float4* src = feats + (size_t)row * (DD / 4);
    float4* dst = (float4*)(out + OUT_FEATS_OFF) + (size_t)row * (DD / 4);

    if (any) {
        #pragma unroll
        for (int i = 0; i < DD / 4 / 32; i++)   // 16 float4 per lane
            dst[lane + 32 * i] = __ldg(&src[lane + 32 * i]);
    } else {
        float4 z = make_float4(0.f, 0.f, 0.f, 0.f);
        #pragma unroll
        for (int i = 0; i < DD / 4 / 32; i++)
            dst[lane + 32 * i] = z;
    }
}

extern "C" void kernel_launch(void* const* d_in, const int* in_sizes, int n_in,
                              void* d_out, int out_size) {
    const float* rois      = (const float*)d_in[0];
    const float* bbox_pred = (const float*)d_in[1];
    const float* scores    = (const float*)d_in[2];
    const float* im_info   = (const float*)d_in[3];
    const float* feats     = (const float*)d_in[4];
    float* out = (float*)d_out;

    fused_kernel<<<GRID, 512>>>(rois, bbox_pred, scores, im_info,
                                (const float4*)feats, out);
}